// round 4
// baseline (speedup 1.0000x reference)
#include <cuda_runtime.h>
#include <cstdint>

// Spacial IRNN: 4 directional relu-scans over [B,C,H,W] = [4,64,256,256] fp32.
// out[dir][b][c][h][w], dir: 0=up, 1=right, 2=down, 3=left.
// h_0 = x_edge (raw), h_t = relu(w_c * h_{t-1} + b_c + x_t).
//
// Fused kernel, TPB=128, role = blockIdx.x % 5:
//   role 0    -> vertical block: one thread per float2 column pair, up+down
//                interleaved (4 independent chains / thread).
//   role 1..4 -> horizontal block: 64 rows; threads 0-63 scan right on tile A,
//                threads 64-127 scan left on tile B. cp.async double-buffered
//                staging, register-resident scan, coalesced STG.128 stcs out.

#define HH 256
#define WW 256
#define BB 4
#define CC 64

constexpr int HW = HH * WW;
constexpr long long DIRSZ = (long long)BB * CC * HH * WW;  // 16,777,216

constexpr int TPB     = 128;
constexpr int VBLOCKS = (BB * CC * WW / 2) / TPB;   // 256
constexpr int HROWS   = 64;
constexpr int HBLOCKS = (BB * CC * HH) / HROWS;     // 1024
constexpr int CHUNK   = 32;
constexpr int NCHUNK  = WW / CHUNK;                 // 8
constexpr int STRIDE  = 36;                          // floats; 144B: 16B-aligned,
                                                     // conflict-free in octet phases
constexpr int TILEF   = HROWS * STRIDE;              // 2304 floats / tile

__device__ __forceinline__ void cp_async16(uint32_t saddr, const void* gptr) {
    asm volatile("cp.async.cg.shared.global [%0], [%1], 16;\n"
                 :: "r"(saddr), "l"(gptr));
}
__device__ __forceinline__ void cp_commit() {
    asm volatile("cp.async.commit_group;\n");
}
__device__ __forceinline__ void cp_wait0() {
    asm volatile("cp.async.wait_group 0;\n");
}

__device__ __forceinline__ float2 step2(float w, float2 s, float b, float2 x) {
    float2 r;
    r.x = fmaxf(fmaf(w, s.x, b + x.x), 0.0f);
    r.y = fmaxf(fmaf(w, s.y, b + x.y), 0.0f);
    return r;
}

__global__ void __launch_bounds__(TPB, 6)
irnn_fused_kernel(const float* __restrict__ x,
                  const float* __restrict__ w_up,    const float* __restrict__ b_up,
                  const float* __restrict__ w_right, const float* __restrict__ b_right,
                  const float* __restrict__ w_down,  const float* __restrict__ b_down,
                  const float* __restrict__ w_left,  const float* __restrict__ b_left,
                  float* __restrict__ out)
{
    // [A0, A1, B0, B1]
    __shared__ float tiles[4][TILEF];

    const int role = blockIdx.x % 5;
    const int grp  = blockIdx.x / 5;
    const int tid  = threadIdx.x;

    if (role == 0) {
        // ---------------- vertical: one thread per (b,c, 2w) ----------------
        const int id = grp * TPB + tid;        // 0 .. 32767
        const int w2 = id & 127;               // W/2 = 128
        const int bc = id >> 7;
        const int c  = bc & (CC - 1);
        const int RS = WW / 2;                 // 128 float2 per row

        const float2* xp = ((const float2*)(x + (size_t)bc * HW)) + w2;
        float2* od = ((float2*)(out + 2 * DIRSZ + (size_t)bc * HW)) + w2;  // down
        float2* ou = ((float2*)(out + 0 * DIRSZ + (size_t)bc * HW)) + w2;  // up

        const float wd = w_down[c], bd = b_down[c];
        const float wu = w_up[c],   bu = b_up[c];

        float2 sd = xp[0];
        float2 su = xp[(HH - 1) * RS];
        __stcs(&od[0], sd);
        __stcs(&ou[(HH - 1) * RS], su);

#pragma unroll 4
        for (int h = 1; h < HH; ++h) {
            float2 xd = xp[h * RS];
            float2 xu = xp[(HH - 1 - h) * RS];
            sd = step2(wd, sd, bd, xd);
            su = step2(wu, su, bu, xu);
            __stcs(&od[h * RS], sd);
            __stcs(&ou[(HH - 1 - h) * RS], su);
        }
    } else {
        // ---------------- horizontal: 64 rows, both directions ---------------
        const int hb = grp * 4 + (role - 1);   // 0 .. 1023
        const int r0 = hb * HROWS;
        const int bc = r0 >> 8;                // uniform within block
        const int c  = bc & (CC - 1);

        const float* xbase = x + (size_t)r0 * WW;
        float* orr = out + 1 * DIRSZ + (size_t)r0 * WW;  // right
        float* ol  = out + 3 * DIRSZ + (size_t)r0 * WW;  // left

        const bool isLeft = (tid >= HROWS);
        const int  r      = tid & (HROWS - 1);

        const float wsc = isLeft ? w_left[c] : w_right[c];
        const float bsc = isLeft ? b_left[c] : b_right[c];

        const uint32_t smem0 =
            (uint32_t)__cvta_generic_to_shared(&tiles[0][0]);

        // staging map: f = k*128+tid, row = f>>3, col4 = f&7 (coalesced 128B)
        const int srow  = tid >> 3;            // base row per k-step offset +16
        const int scol4 = tid & 7;

        // stage chunk ch into buffer buf (both tiles)
        auto stage = [&](int ch, int buf) {
            const int wA = ch * CHUNK;
            const int wB = (NCHUNK - 1 - ch) * CHUNK;
            const uint32_t baseA = smem0 + (uint32_t)(buf * TILEF) * 4u;
            const uint32_t baseB = smem0 + (uint32_t)((2 + buf) * TILEF) * 4u;
#pragma unroll
            for (int k = 0; k < 4; ++k) {
                int row  = srow + k * 16;
                uint32_t off = (uint32_t)(row * STRIDE + scol4 * 4) * 4u;
                cp_async16(baseA + off, &xbase[(size_t)row * WW + wA + scol4 * 4]);
                cp_async16(baseB + off, &xbase[(size_t)row * WW + wB + scol4 * 4]);
            }
            cp_commit();
        };

        stage(0, 0);

        float s = 0.0f;
        for (int ch = 0; ch < NCHUNK; ++ch) {
            const int buf = ch & 1;
            cp_wait0();
            __syncthreads();                     // staged data visible; prior
                                                 // gathers complete
            if (ch < NCHUNK - 1) stage(ch + 1, buf ^ 1);

            // ---- load own row into registers (LDS.128, conflict-free) ----
            float* tr = &tiles[(isLeft ? 2 : 0) + buf][r * STRIDE];
            float4 v[8];
#pragma unroll
            for (int q = 0; q < 8; ++q) v[q] = *(float4*)&tr[q * 4];
            float* a = (float*)v;

            // ---- register-resident scan chain ----
            if (!isLeft) {
#pragma unroll
                for (int t = 0; t < CHUNK; ++t) {
                    float xv = a[t];
                    if (t == 0)
                        s = (ch == 0) ? xv : fmaxf(fmaf(wsc, s, bsc + xv), 0.0f);
                    else
                        s = fmaxf(fmaf(wsc, s, bsc + xv), 0.0f);
                    a[t] = s;
                }
            } else {
#pragma unroll
                for (int t = CHUNK - 1; t >= 0; --t) {
                    float xv = a[t];
                    if (t == CHUNK - 1)
                        s = (ch == 0) ? xv : fmaxf(fmaf(wsc, s, bsc + xv), 0.0f);
                    else
                        s = fmaxf(fmaf(wsc, s, bsc + xv), 0.0f);
                    a[t] = s;
                }
            }

            // ---- write results back (STS.128) ----
#pragma unroll
            for (int q = 0; q < 8; ++q) *(float4*)&tr[q * 4] = v[q];
            __syncthreads();                     // scans visible

            // ---- gather + coalesced streaming stores ----
            const int wA = ch * CHUNK;
            const int wB = (NCHUNK - 1 - ch) * CHUNK;
            float* tileA = &tiles[0 + buf][0];
            float* tileB = &tiles[2 + buf][0];
#pragma unroll
            for (int k = 0; k < 4; ++k) {
                int row = srow + k * 16;
                int off = row * STRIDE + scol4 * 4;
                float4 va = *(float4*)&tileA[off];
                float4 vb = *(float4*)&tileB[off];
                __stcs((float4*)&orr[(size_t)row * WW + wA + scol4 * 4], va);
                __stcs((float4*)&ol [(size_t)row * WW + wB + scol4 * 4], vb);
            }
        }
    }
}

extern "C" void kernel_launch(void* const* d_in, const int* in_sizes, int n_in,
                              void* d_out, int out_size)
{
    const float* x       = (const float*)d_in[0];
    const float* w_up    = (const float*)d_in[1];
    const float* w_right = (const float*)d_in[2];
    const float* w_down  = (const float*)d_in[3];
    const float* w_left  = (const float*)d_in[4];
    const float* b_up    = (const float*)d_in[5];
    const float* b_right = (const float*)d_in[6];
    const float* b_down  = (const float*)d_in[7];
    const float* b_left  = (const float*)d_in[8];
    float* out = (float*)d_out;

    int grid = VBLOCKS + HBLOCKS;   // 256 + 1024 = 1280 (= 256 * 5)
    irnn_fused_kernel<<<grid, TPB>>>(x,
                                     w_up, b_up, w_right, b_right,
                                     w_down, b_down, w_left, b_left,
                                     out);
}

// round 5
// speedup vs baseline: 1.5680x; 1.5680x over previous
#include <cuda_runtime.h>

// Spacial IRNN: 4 directional relu-scans over [B,C,H,W] = [4,64,256,256] fp32.
// out[dir][b][c][h][w], dir: 0=up, 1=right, 2=down, 3=left.
// h_0 = x_edge (raw), h_t = relu(w_c * h_{t-1} + b_c + x_t).
//
// R2 chassis (best parallelism: 768x256, occ 53%) + R3's validated traffic
// reduction (__stcs streaming stores keep the input resident in L2 for the
// reverse-direction re-read). role = blockIdx.x % 3:
//   role 0   -> vertical block (up+down interleaved chains, ILP=2)
//   role 1,2 -> horizontal block (128 rows; threads 0-127 scan right,
//               threads 128-255 scan left on a second tile)

#define HH 256
#define WW 256
#define BB 4
#define CC 64

constexpr int HW = HH * WW;
constexpr long long DIRSZ = (long long)BB * CC * HH * WW;  // 16,777,216

constexpr int TPB     = 256;
constexpr int VBLOCKS = (BB * CC * WW) / TPB;   // 256
constexpr int HROWS   = 128;
constexpr int HBLOCKS = (BB * CC * HH) / HROWS; // 512
constexpr int CHUNK   = 32;
constexpr int NCHUNK  = WW / CHUNK;             // 8

__global__ void __launch_bounds__(TPB, 5)
irnn_fused_kernel(const float* __restrict__ x,
                  const float* __restrict__ w_up,    const float* __restrict__ b_up,
                  const float* __restrict__ w_right, const float* __restrict__ b_right,
                  const float* __restrict__ w_down,  const float* __restrict__ b_down,
                  const float* __restrict__ w_left,  const float* __restrict__ b_left,
                  float* __restrict__ out)
{
    __shared__ float tA[HROWS][CHUNK + 1];   // right-direction staging
    __shared__ float tB[HROWS][CHUNK + 1];   // left-direction staging

    const int role = blockIdx.x % 3;
    const int grp  = blockIdx.x / 3;
    const int tid  = threadIdx.x;

    if (role == 0) {
        // ------------------- vertical: one thread per (b,c,w) column --------
        int id = grp * TPB + tid;            // 0 .. B*C*W-1
        int w  = id & (WW - 1);
        int bc = id >> 8;
        int c  = bc & (CC - 1);

        const float* xp = x + (size_t)bc * HW + w;
        float* od = out + 2 * DIRSZ + (size_t)bc * HW + w;  // down
        float* ou = out + 0 * DIRSZ + (size_t)bc * HW + w;  // up

        const float wd = w_down[c], bd = b_down[c];
        const float wu = w_up[c],   bu = b_up[c];

        float sd = xp[0];
        float su = xp[(HH - 1) * WW];
        __stcs(&od[0], sd);
        __stcs(&ou[(HH - 1) * WW], su);

#pragma unroll 8
        for (int h = 1; h < HH; ++h) {
            float xd = xp[h * WW];
            float xu = xp[(HH - 1 - h) * WW];
            sd = fmaxf(fmaf(wd, sd, bd + xd), 0.0f);
            su = fmaxf(fmaf(wu, su, bu + xu), 0.0f);
            __stcs(&od[h * WW], sd);
            __stcs(&ou[(HH - 1 - h) * WW], su);
        }
    } else {
        // ------------------- horizontal: 128 rows, both directions ----------
        const int hb = grp * 2 + (role - 1);     // 0 .. 511
        const int r0 = hb * HROWS;               // first global row
        const int bc = r0 >> 8;                  // uniform within block
        const int c  = bc & (CC - 1);

        const float* xbase = x + (size_t)r0 * WW;
        float* orr = out + 1 * DIRSZ + (size_t)r0 * WW;  // right
        float* ol  = out + 3 * DIRSZ + (size_t)r0 * WW;  // left

        const bool isLeft = (tid >= HROWS);
        const int  r      = tid & (HROWS - 1);           // owned row

        const float wsc = isLeft ? w_left[c] : w_right[c];
        const float bsc = isLeft ? b_left[c] : b_right[c];

        // staging map: affine in k -> low register pressure, fully coalesced
        const int colL = tid & (CHUNK - 1);
        const int rowB = tid >> 5;                       // 0..7

        float s = 0.0f;
        for (int ch = 0; ch < NCHUNK; ++ch) {
            const int wA = ch * CHUNK;                   // right chunk (fwd)
            const int wB = (NCHUNK - 1 - ch) * CHUNK;    // left  chunk (bwd)

            // load both tiles cooperatively (coalesced 128B lines)
#pragma unroll
            for (int k = 0; k < 16; ++k) {
                int row = rowB + k * 8;
                tA[row][colL] = xbase[(size_t)row * WW + wA + colL];
                tB[row][colL] = xbase[(size_t)row * WW + wB + colL];
            }
            __syncthreads();

            // scan owned row in smem (stride 33 -> conflict-free)
            if (!isLeft) {
#pragma unroll
                for (int t = 0; t < CHUNK; ++t) {
                    float xv = tA[r][t];
                    if (ch == 0 && t == 0) s = xv;
                    else s = fmaxf(fmaf(wsc, s, bsc + xv), 0.0f);
                    tA[r][t] = s;
                }
            } else {
#pragma unroll
                for (int t = CHUNK - 1; t >= 0; --t) {
                    float xv = tB[r][t];
                    if (ch == 0 && t == CHUNK - 1) s = xv;
                    else s = fmaxf(fmaf(wsc, s, bsc + xv), 0.0f);
                    tB[r][t] = s;
                }
            }
            __syncthreads();

            // store both tiles (coalesced, streaming — evict-first in L2)
#pragma unroll
            for (int k = 0; k < 16; ++k) {
                int row = rowB + k * 8;
                __stcs(&orr[(size_t)row * WW + wA + colL], tA[row][colL]);
                __stcs(&ol [(size_t)row * WW + wB + colL], tB[row][colL]);
            }
            __syncthreads();
        }
    }
}

extern "C" void kernel_launch(void* const* d_in, const int* in_sizes, int n_in,
                              void* d_out, int out_size)
{
    const float* x       = (const float*)d_in[0];
    const float* w_up    = (const float*)d_in[1];
    const float* w_right = (const float*)d_in[2];
    const float* w_down  = (const float*)d_in[3];
    const float* w_left  = (const float*)d_in[4];
    const float* b_up    = (const float*)d_in[5];
    const float* b_right = (const float*)d_in[6];
    const float* b_down  = (const float*)d_in[7];
    const float* b_left  = (const float*)d_in[8];
    float* out = (float*)d_out;

    int grid = VBLOCKS + HBLOCKS;   // 256 vertical + 512 horizontal = 768
    irnn_fused_kernel<<<grid, TPB>>>(x,
                                     w_up, b_up, w_right, b_right,
                                     w_down, b_down, w_left, b_left,
                                     out);
}

// round 6
// speedup vs baseline: 1.9856x; 1.2663x over previous
#include <cuda_runtime.h>

// Spacial IRNN: 4 directional relu-scans over [B,C,H,W] = [4,64,256,256] fp32.
// out[dir][b][c][h][w], dir: 0=up, 1=right, 2=down, 3=left.
// h_0 = x_edge (raw), h_t = relu(w_c * h_{t-1} + b_c + x_t).
//
// role = blockIdx.x % 3:
//   role 0   -> vertical block (up+down interleaved chains, ILP=2, stcs out)
//   role 1,2 -> horizontal block: warp-specialized. Threads 0-127 process the
//               "right" direction on tile A, threads 128-255 "left" on tile B.
//               Each group syncs on its own named barrier -> phases of the two
//               groups overlap. All smem/global I/O is float4 (stride-36 tile,
//               conflict-free in every phase).

#define HH 256
#define WW 256
#define BB 4
#define CC 64

constexpr int HW = HH * WW;
constexpr long long DIRSZ = (long long)BB * CC * HH * WW;  // 16,777,216

constexpr int TPB     = 256;
constexpr int VBLOCKS = (BB * CC * WW) / TPB;   // 256
constexpr int HROWS   = 128;
constexpr int HBLOCKS = (BB * CC * HH) / HROWS; // 512
constexpr int CHUNK   = 32;
constexpr int NCHUNK  = WW / CHUNK;             // 8
constexpr int STRIDE  = 36;                     // floats; 144B row: 16B-aligned

__device__ __forceinline__ void bar_group(int id) {
    asm volatile("bar.sync %0, 128;" :: "r"(id) : "memory");
}

__global__ void __launch_bounds__(TPB, 5)
irnn_fused_kernel(const float* __restrict__ x,
                  const float* __restrict__ w_up,    const float* __restrict__ b_up,
                  const float* __restrict__ w_right, const float* __restrict__ b_right,
                  const float* __restrict__ w_down,  const float* __restrict__ b_down,
                  const float* __restrict__ w_left,  const float* __restrict__ b_left,
                  float* __restrict__ out)
{
    __shared__ float tiles[2][HROWS * STRIDE];   // [0]=right(A), [1]=left(B)

    const int role = blockIdx.x % 3;
    const int grp  = blockIdx.x / 3;
    const int tid  = threadIdx.x;

    if (role == 0) {
        // ------------------- vertical: one thread per (b,c,w) column --------
        int id = grp * TPB + tid;            // 0 .. B*C*W-1
        int w  = id & (WW - 1);
        int bc = id >> 8;
        int c  = bc & (CC - 1);

        const float* xp = x + (size_t)bc * HW + w;
        float* od = out + 2 * DIRSZ + (size_t)bc * HW + w;  // down
        float* ou = out + 0 * DIRSZ + (size_t)bc * HW + w;  // up

        const float wd = w_down[c], bd = b_down[c];
        const float wu = w_up[c],   bu = b_up[c];

        float sd = xp[0];
        float su = xp[(HH - 1) * WW];
        __stcs(&od[0], sd);
        __stcs(&ou[(HH - 1) * WW], su);

#pragma unroll 8
        for (int h = 1; h < HH; ++h) {
            float xd = xp[h * WW];
            float xu = xp[(HH - 1 - h) * WW];
            sd = fmaxf(fmaf(wd, sd, bd + xd), 0.0f);
            su = fmaxf(fmaf(wu, su, bu + xu), 0.0f);
            __stcs(&od[h * WW], sd);
            __stcs(&ou[(HH - 1 - h) * WW], su);
        }
    } else {
        // ------------------- horizontal: 128 rows, warp-specialized ---------
        const int hb = grp * 2 + (role - 1);     // 0 .. 511
        const int r0 = hb * HROWS;               // first global row
        const int bc = r0 >> 8;                  // uniform within block
        const int c  = bc & (CC - 1);

        const bool isLeft = (tid >= HROWS);
        const int  gt     = tid & (HROWS - 1);   // thread id within group
        const int  barid  = isLeft ? 2 : 1;

        const float* xbase = x + (size_t)r0 * WW;
        float* obase = out + (isLeft ? 3 : 1) * DIRSZ + (size_t)r0 * WW;

        const float wsc = isLeft ? w_left[c] : w_right[c];
        const float bsc = isLeft ? b_left[c] : b_right[c];

        float* tile = &tiles[isLeft ? 1 : 0][0];

        // staging map: f = k*128 + gt ; row = f>>3 ; col4 = f&7
        const int srow  = gt >> 3;               // base row, +16 per k
        const int scol4 = gt & 7;

        float s = 0.0f;
        for (int ch = 0; ch < NCHUNK; ++ch) {
            // group A walks chunks forward, group B backward
            const int wX = (isLeft ? (NCHUNK - 1 - ch) : ch) * CHUNK;

            // ---- load: LDG.128 -> STS.128 (conflict-free) ----
#pragma unroll
            for (int k = 0; k < 8; ++k) {
                int row = srow + k * 16;
                float4 v = *(const float4*)&xbase[(size_t)row * WW + wX + scol4 * 4];
                *(float4*)&tile[row * STRIDE + scol4 * 4] = v;
            }
            bar_group(barid);

            // ---- scan owned row gt, register-resident, two 16-float halves
            float* tr = &tile[gt * STRIDE];
            if (!isLeft) {
#pragma unroll
                for (int half = 0; half < 2; ++half) {
                    float4 v[4];
#pragma unroll
                    for (int q = 0; q < 4; ++q) v[q] = *(float4*)&tr[(half * 4 + q) * 4];
                    float* a = (float*)v;
#pragma unroll
                    for (int t = 0; t < 16; ++t) {
                        float xv = a[t];
                        if (ch == 0 && half == 0 && t == 0) s = xv;
                        else s = fmaxf(fmaf(wsc, s, bsc + xv), 0.0f);
                        a[t] = s;
                    }
#pragma unroll
                    for (int q = 0; q < 4; ++q) *(float4*)&tr[(half * 4 + q) * 4] = v[q];
                }
            } else {
#pragma unroll
                for (int half = 1; half >= 0; --half) {
                    float4 v[4];
#pragma unroll
                    for (int q = 0; q < 4; ++q) v[q] = *(float4*)&tr[(half * 4 + q) * 4];
                    float* a = (float*)v;
#pragma unroll
                    for (int t = 15; t >= 0; --t) {
                        float xv = a[t];
                        if (ch == 0 && half == 1 && t == 15) s = xv;
                        else s = fmaxf(fmaf(wsc, s, bsc + xv), 0.0f);
                        a[t] = s;
                    }
#pragma unroll
                    for (int q = 0; q < 4; ++q) *(float4*)&tr[(half * 4 + q) * 4] = v[q];
                }
            }
            bar_group(barid);

            // ---- store: LDS.128 -> STG.128 streaming ----
#pragma unroll
            for (int k = 0; k < 8; ++k) {
                int row = srow + k * 16;
                float4 v = *(float4*)&tile[row * STRIDE + scol4 * 4];
                __stcs((float4*)&obase[(size_t)row * WW + wX + scol4 * 4], v);
            }
            bar_group(barid);   // tile reads done before next chunk overwrites
        }
    }
}

extern "C" void kernel_launch(void* const* d_in, const int* in_sizes, int n_in,
                              void* d_out, int out_size)
{
    const float* x       = (const float*)d_in[0];
    const float* w_up    = (const float*)d_in[1];
    const float* w_right = (const float*)d_in[2];
    const float* w_down  = (const float*)d_in[3];
    const float* w_left  = (const float*)d_in[4];
    const float* b_up    = (const float*)d_in[5];
    const float* b_right = (const float*)d_in[6];
    const float* b_down  = (const float*)d_in[7];
    const float* b_left  = (const float*)d_in[8];
    float* out = (float*)d_out;

    int grid = VBLOCKS + HBLOCKS;   // 256 vertical + 512 horizontal = 768
    irnn_fused_kernel<<<grid, TPB>>>(x,
                                     w_up, b_up, w_right, b_right,
                                     w_down, b_down, w_left, b_left,
                                     out);
}